// round 1
// baseline (speedup 1.0000x reference)
#include <cuda_runtime.h>
#include <math.h>

// Problem constants
#define BB      2
#define SS      2048
#define INDIM   1024
#define QH_     16
#define KVH_    4
#define HD_     64
#define G_      4
#define NKV     256      // KVH_*HD_

// Scratch (device globals: allocation-free, graph-capturable)
__device__ float g_Wqs[INDIM * NKV];            // group-folded Wq  [K=1024][N=256]
__device__ float g_Q[BB * KVH_ * SS * HD_];     // [b][h][s][d]
__device__ float g_K[BB * KVH_ * SS * HD_];
__device__ float g_V[BB * KVH_ * SS * HD_];
__device__ float g_AO[BB * SS * NKV];           // attention out [b][s][h*64+d]

// ---------------------------------------------------------------------------
// Fold Wq over the group axis: Wq_sum[i,h,d] = sum_g Wq[i, h*G+g, d]
// ---------------------------------------------------------------------------
__global__ void fold_wq_kernel(const float* __restrict__ Wq) {
    int idx = blockIdx.x * blockDim.x + threadIdx.x;
    if (idx >= INDIM * NKV) return;
    int i = idx >> 8;            // / 256
    int n = idx & 255;
    int h = n >> 6, d = n & 63;
    const float* p = Wq + (size_t)i * (QH_ * HD_) + (size_t)(h * G_) * HD_ + d;
    g_Wqs[idx] = p[0] + p[HD_] + p[2 * HD_] + p[3 * HD_];
}

// ---------------------------------------------------------------------------
// Tiled fp32 GEMM: C[4096, N] = A[4096, KD] * B[KD, N]
// Block tile 128x64, BK=16, 256 threads, 8x4 microtile per thread.
// SCATTER=true writes C into [b][h][s][d] layout (for Q/K/V).
// ---------------------------------------------------------------------------
template<int KD, bool SCATTER>
__global__ void __launch_bounds__(256) gemm_kernel(
        const float* __restrict__ A, const float* __restrict__ Bm,
        float* __restrict__ C, int N) {
    __shared__ float As[16][132];   // [k][m], padded
    __shared__ float Bs[16][64];    // [k][n]

    int tid = threadIdx.x;
    int m0 = blockIdx.y * 128;
    int n0 = blockIdx.x * 64;
    int ty = tid >> 4, tx = tid & 15;

    float acc[8][4];
    #pragma unroll
    for (int i = 0; i < 8; i++)
        #pragma unroll
        for (int j = 0; j < 4; j++) acc[i][j] = 0.f;

    int la_r = tid >> 2;            // 0..63
    int la_c = (tid & 3) << 2;      // 0,4,8,12
    int lb_r = tid >> 4;            // 0..15
    int lb_c = (tid & 15) << 2;     // 0..60

    for (int k0 = 0; k0 < KD; k0 += 16) {
        #pragma unroll
        for (int rr = 0; rr < 2; rr++) {
            int m = m0 + la_r + rr * 64;
            float4 a = *(const float4*)&A[(size_t)m * KD + k0 + la_c];
            As[la_c + 0][la_r + rr * 64] = a.x;
            As[la_c + 1][la_r + rr * 64] = a.y;
            As[la_c + 2][la_r + rr * 64] = a.z;
            As[la_c + 3][la_r + rr * 64] = a.w;
        }
        *(float4*)&Bs[lb_r][lb_c] =
            *(const float4*)&Bm[(size_t)(k0 + lb_r) * N + n0 + lb_c];
        __syncthreads();

        #pragma unroll
        for (int kk = 0; kk < 16; kk++) {
            float4 a0 = *(const float4*)&As[kk][ty * 8];
            float4 a1 = *(const float4*)&As[kk][ty * 8 + 4];
            float4 b  = *(const float4*)&Bs[kk][tx * 4];
            float av[8] = {a0.x, a0.y, a0.z, a0.w, a1.x, a1.y, a1.z, a1.w};
            float bv[4] = {b.x, b.y, b.z, b.w};
            #pragma unroll
            for (int i = 0; i < 8; i++)
                #pragma unroll
                for (int j = 0; j < 4; j++)
                    acc[i][j] += av[i] * bv[j];
        }
        __syncthreads();
    }

    #pragma unroll
    for (int i = 0; i < 8; i++) {
        int m = m0 + ty * 8 + i;
        float4 o = make_float4(acc[i][0], acc[i][1], acc[i][2], acc[i][3]);
        if (SCATTER) {
            int b = m >> 11;
            int s = m & 2047;
            int h = n0 >> 6;                  // BN=64 aligns with heads
            size_t off = (((size_t)(b * KVH_ + h) * SS + s) << 6) + (size_t)(tx << 2);
            *(float4*)&C[off] = o;
        } else {
            *(float4*)&C[(size_t)m * N + n0 + (tx << 2)] = o;
        }
    }
}

// ---------------------------------------------------------------------------
// Causal flash attention, fp32. One block = one 64-row Q tile of one (b,h).
// Online softmax; scale 1/8 folded into Q at load (exact: power of two).
// P tile aliases the K smem buffer -> 48KB static smem total.
// ---------------------------------------------------------------------------
__global__ void __launch_bounds__(256) attn_kernel() {
    __shared__ float Qs[64 * 64];
    __shared__ float KPs[64 * 64];   // K tile, then reused for P
    __shared__ float Vs[64 * 64];

    int bh = blockIdx.y;   // b*4 + h
    int qt = blockIdx.x;   // q tile index
    const float* Qh = g_Q + (size_t)bh * SS * HD_;
    const float* Kh = g_K + (size_t)bh * SS * HD_;
    const float* Vh = g_V + (size_t)bh * SS * HD_;

    int tid = threadIdx.x;
    int ty = tid >> 4, tx = tid & 15;
    int q0 = qt * 64;

    #pragma unroll
    for (int it = 0; it < 4; it++) {
        int o = (tid + it * 256) * 4;
        float4 q = *(const float4*)&Qh[(size_t)q0 * 64 + o];
        q.x *= 0.125f; q.y *= 0.125f; q.z *= 0.125f; q.w *= 0.125f;
        *(float4*)&Qs[o] = q;
    }

    float m_i[4], l_i[4], acc[4][4];
    #pragma unroll
    for (int i = 0; i < 4; i++) {
        m_i[i] = -3.0e38f; l_i[i] = 0.f;
        #pragma unroll
        for (int j = 0; j < 4; j++) acc[i][j] = 0.f;
    }

    for (int kt = 0; kt <= qt; kt++) {
        __syncthreads();   // previous PV reads of KPs/Vs done
        #pragma unroll
        for (int it = 0; it < 4; it++) {
            int o = (tid + it * 256) * 4;
            *(float4*)&KPs[o] = *(const float4*)&Kh[(size_t)kt * 4096 + o];
            *(float4*)&Vs[o]  = *(const float4*)&Vh[(size_t)kt * 4096 + o];
        }
        __syncthreads();

        // --- scores: 4x4 microtile per thread ---
        float sreg[4][4];
        #pragma unroll
        for (int i = 0; i < 4; i++)
            #pragma unroll
            for (int j = 0; j < 4; j++) sreg[i][j] = 0.f;

        for (int d = 0; d < 64; d += 4) {
            float4 qv[4], kv[4];
            #pragma unroll
            for (int i = 0; i < 4; i++) qv[i] = *(const float4*)&Qs[(ty * 4 + i) * 64 + d];
            #pragma unroll
            for (int j = 0; j < 4; j++) kv[j] = *(const float4*)&KPs[(tx * 4 + j) * 64 + d];
            #pragma unroll
            for (int i = 0; i < 4; i++)
                #pragma unroll
                for (int j = 0; j < 4; j++)
                    sreg[i][j] += qv[i].x * kv[j].x + qv[i].y * kv[j].y +
                                  qv[i].z * kv[j].z + qv[i].w * kv[j].w;
        }
        __syncthreads();   // all K reads complete before P overwrite

        if (kt == qt) {    // causal mask only on the diagonal tile
            #pragma unroll
            for (int i = 0; i < 4; i++)
                #pragma unroll
                for (int j = 0; j < 4; j++)
                    if (ty * 4 + i < tx * 4 + j) sreg[i][j] = -3.0e38f;
        }

        // --- online softmax (row stats shared across the 16 tx threads) ---
        #pragma unroll
        for (int i = 0; i < 4; i++) {
            float mx = fmaxf(fmaxf(sreg[i][0], sreg[i][1]),
                             fmaxf(sreg[i][2], sreg[i][3]));
            #pragma unroll
            for (int off = 1; off < 16; off <<= 1)
                mx = fmaxf(mx, __shfl_xor_sync(0xffffffffu, mx, off));
            float mnew = fmaxf(m_i[i], mx);
            float corr = __expf(m_i[i] - mnew);
            float rs = 0.f;
            #pragma unroll
            for (int j = 0; j < 4; j++) {
                float p = __expf(sreg[i][j] - mnew);
                sreg[i][j] = p;
                rs += p;
            }
            #pragma unroll
            for (int off = 1; off < 16; off <<= 1)
                rs += __shfl_xor_sync(0xffffffffu, rs, off);
            l_i[i] = l_i[i] * corr + rs;
            m_i[i] = mnew;
            #pragma unroll
            for (int j = 0; j < 4; j++) acc[i][j] *= corr;
        }

        // --- write P (into KPs alias) ---
        #pragma unroll
        for (int i = 0; i < 4; i++)
            *(float4*)&KPs[(ty * 4 + i) * 64 + tx * 4] =
                make_float4(sreg[i][0], sreg[i][1], sreg[i][2], sreg[i][3]);
        __syncthreads();

        // --- PV accumulate: O[4 rows][4 dims] per thread ---
        #pragma unroll 4
        for (int jj = 0; jj < 64; jj++) {
            float4 v = *(const float4*)&Vs[jj * 64 + tx * 4];
            #pragma unroll
            for (int i = 0; i < 4; i++) {
                float p = KPs[(ty * 4 + i) * 64 + jj];
                acc[i][0] += p * v.x;
                acc[i][1] += p * v.y;
                acc[i][2] += p * v.z;
                acc[i][3] += p * v.w;
            }
        }
    }

    // epilogue: normalize and write to [b][s][h*64+d]
    int b = bh >> 2, h = bh & 3;
    #pragma unroll
    for (int i = 0; i < 4; i++) {
        float inv = 1.0f / l_i[i];
        int row = q0 + ty * 4 + i;
        float4 o = make_float4(acc[i][0] * inv, acc[i][1] * inv,
                               acc[i][2] * inv, acc[i][3] * inv);
        size_t off = (((size_t)b * SS + row) << 8) + (size_t)(h << 6) + (size_t)(tx << 2);
        *(float4*)&g_AO[off] = o;
    }
}

// ---------------------------------------------------------------------------
// Launch: fold -> Q/K/V projections -> attention -> output projection
// Inputs: 0 q_in, 1 kv_in, 2 mask(ignored: provably causal), 3 Wq, 4 Wk, 5 Wv, 6 Wo
// ---------------------------------------------------------------------------
extern "C" void kernel_launch(void* const* d_in, const int* in_sizes, int n_in,
                              void* d_out, int out_size) {
    const float* q_in  = (const float*)d_in[0];
    const float* kv_in = (const float*)d_in[1];
    const float* Wq    = (const float*)d_in[3];
    const float* Wk    = (const float*)d_in[4];
    const float* Wv    = (const float*)d_in[5];
    const float* Wo    = (const float*)d_in[6];
    float* out = (float*)d_out;

    float *pWqs, *pQ, *pK, *pV, *pAO;
    cudaGetSymbolAddress((void**)&pWqs, g_Wqs);
    cudaGetSymbolAddress((void**)&pQ,   g_Q);
    cudaGetSymbolAddress((void**)&pK,   g_K);
    cudaGetSymbolAddress((void**)&pV,   g_V);
    cudaGetSymbolAddress((void**)&pAO,  g_AO);

    fold_wq_kernel<<<(INDIM * NKV + 255) / 256, 256>>>(Wq);

    dim3 gqkv(NKV / 64, (BB * SS) / 128);   // (4, 32)
    gemm_kernel<INDIM, true><<<gqkv, 256>>>(q_in,  pWqs, pQ, NKV);
    gemm_kernel<INDIM, true><<<gqkv, 256>>>(kv_in, Wk,   pK, NKV);
    gemm_kernel<INDIM, true><<<gqkv, 256>>>(kv_in, Wv,   pV, NKV);

    attn_kernel<<<dim3(SS / 64, BB * KVH_), 256>>>();

    gemm_kernel<NKV, false><<<dim3(INDIM / 64, (BB * SS) / 128), 256>>>(pAO, Wo, out, INDIM);
}

// round 2
// speedup vs baseline: 1.6393x; 1.6393x over previous
#include <cuda_runtime.h>
#include <math.h>

#define BB      2
#define SS      2048
#define INDIM   1024
#define QH_     16
#define KVH_    4
#define HD_     64
#define G_      4
#define NKV     256

__device__ float g_Wqs[INDIM * NKV];
__device__ float g_Q[BB * KVH_ * SS * HD_];
__device__ float g_K[BB * KVH_ * SS * HD_];
__device__ float g_V[BB * KVH_ * SS * HD_];
__device__ float g_AO[BB * SS * NKV];

// ---------------------------------------------------------------------------
// Fold Wq over group axis: Wq_sum[i,h,d] = sum_g Wq[i, h*G+g, d]
// ---------------------------------------------------------------------------
__global__ void fold_wq_kernel(const float* __restrict__ Wq) {
    int idx = blockIdx.x * blockDim.x + threadIdx.x;
    if (idx >= INDIM * NKV) return;
    int i = idx >> 8;
    int n = idx & 255;
    int h = n >> 6, d = n & 63;
    const float* p = Wq + (size_t)i * (QH_ * HD_) + (size_t)(h * G_) * HD_ + d;
    g_Wqs[idx] = p[0] + p[HD_] + p[2 * HD_] + p[3 * HD_];
}

// ---------------------------------------------------------------------------
// GEMM body: C[4096, N] = A[4096, KD] * B[KD, N]
// 128x64 block tile, BK=16, 256 threads, 8x4 microtile, double-buffered smem
// with register prefetch. SCATTER writes into [b][h][s][d].
// ---------------------------------------------------------------------------
template<int KD, int N, bool SCATTER>
__device__ __forceinline__ void gemm_body(
        const float* __restrict__ A, const float* __restrict__ Bm,
        float* __restrict__ C) {
    __shared__ float As[2][16][132];
    __shared__ float Bs[2][16][64];

    int tid = threadIdx.x;
    int m0 = blockIdx.y * 128;
    int n0 = blockIdx.x * 64;
    int ty = tid >> 4, tx = tid & 15;

    int la_r = tid >> 2;           // 0..63
    int la_c = (tid & 3) << 2;     // 0,4,8,12
    int lb_r = tid >> 4;           // 0..15
    int lb_c = (tid & 15) << 2;    // 0..60

    const float* Ap = A + (size_t)(m0 + la_r) * KD + la_c;
    const float* Bp = Bm + (size_t)lb_r * N + n0 + lb_c;

    float acc[8][4];
    #pragma unroll
    for (int i = 0; i < 8; i++)
        #pragma unroll
        for (int j = 0; j < 4; j++) acc[i][j] = 0.f;

    // prologue: tile 0 -> buf 0
    {
        float4 a0 = *(const float4*)(Ap);
        float4 a1 = *(const float4*)(Ap + (size_t)64 * KD);
        float4 b4 = *(const float4*)(Bp);
        #pragma unroll
        for (int j = 0; j < 4; j++) {
            As[0][la_c + j][la_r]      = ((const float*)&a0)[j];
            As[0][la_c + j][la_r + 64] = ((const float*)&a1)[j];
        }
        *(float4*)&Bs[0][lb_r][lb_c] = b4;
    }
    __syncthreads();

    const int KT = KD / 16;
    int buf = 0;
    #pragma unroll 1
    for (int t = 0; t < KT; t++) {
        bool more = (t + 1 < KT);
        float4 na0, na1, nb4;
        if (more) {
            int k0 = (t + 1) * 16;
            na0 = *(const float4*)(Ap + k0);
            na1 = *(const float4*)(Ap + (size_t)64 * KD + k0);
            nb4 = *(const float4*)(Bp + (size_t)k0 * N);
        }
        #pragma unroll
        for (int kk = 0; kk < 16; kk++) {
            float4 x0 = *(const float4*)&As[buf][kk][ty * 8];
            float4 x1 = *(const float4*)&As[buf][kk][ty * 8 + 4];
            float4 y  = *(const float4*)&Bs[buf][kk][tx * 4];
            float av[8] = {x0.x, x0.y, x0.z, x0.w, x1.x, x1.y, x1.z, x1.w};
            float bv[4] = {y.x, y.y, y.z, y.w};
            #pragma unroll
            for (int i = 0; i < 8; i++)
                #pragma unroll
                for (int j = 0; j < 4; j++)
                    acc[i][j] += av[i] * bv[j];
        }
        if (more) {
            int nb = buf ^ 1;
            #pragma unroll
            for (int j = 0; j < 4; j++) {
                As[nb][la_c + j][la_r]      = ((const float*)&na0)[j];
                As[nb][la_c + j][la_r + 64] = ((const float*)&na1)[j];
            }
            *(float4*)&Bs[nb][lb_r][lb_c] = nb4;
        }
        __syncthreads();
        buf ^= 1;
    }

    #pragma unroll
    for (int i = 0; i < 8; i++) {
        int m = m0 + ty * 8 + i;
        float4 o = make_float4(acc[i][0], acc[i][1], acc[i][2], acc[i][3]);
        if (SCATTER) {
            int b = m >> 11;
            int s = m & 2047;
            int h = n0 >> 6;
            size_t off = (((size_t)(b * KVH_ + h) * SS + s) << 6) + (size_t)(tx << 2);
            *(float4*)&C[off] = o;
        } else {
            *(float4*)&C[(size_t)m * N + n0 + (tx << 2)] = o;
        }
    }
}

// Fused QKV projection: z=0 -> Q (folded weights), z=1 -> K, z=2 -> V
__global__ void __launch_bounds__(256) qkv_gemm_kernel(
        const float* __restrict__ q_in, const float* __restrict__ kv_in,
        const float* __restrict__ Wk, const float* __restrict__ Wv,
        float* __restrict__ Q, float* __restrict__ K, float* __restrict__ V) {
    int z = blockIdx.z;
    const float* A  = (z == 0) ? q_in : kv_in;
    const float* Bm = (z == 0) ? g_Wqs : ((z == 1) ? Wk : Wv);
    float* C        = (z == 0) ? Q : ((z == 1) ? K : V);
    gemm_body<INDIM, NKV, true>(A, Bm, C);
}

__global__ void __launch_bounds__(256) out_gemm_kernel(
        const float* __restrict__ A, const float* __restrict__ Bm,
        float* __restrict__ C) {
    gemm_body<NKV, INDIM, false>(A, Bm, C);
}

// ---------------------------------------------------------------------------
// Causal flash attention, fp32. One CTA handles TWO q-tiles: qp and 31-qp
// -> every CTA does exactly 33 KV tiles (perfect balance).
// ---------------------------------------------------------------------------
__global__ void __launch_bounds__(256) attn_kernel() {
    __shared__ float Qs[64 * 64];
    __shared__ float KPs[64 * 64];   // K tile, aliased as P tile
    __shared__ float Vs[64 * 64];

    int bh = blockIdx.y;
    int qp = blockIdx.x;   // 0..15
    const float* Qh = g_Q + (size_t)bh * SS * HD_;
    const float* Kh = g_K + (size_t)bh * SS * HD_;
    const float* Vh = g_V + (size_t)bh * SS * HD_;

    int tid = threadIdx.x;
    int ty = tid >> 4, tx = tid & 15;
    int b = bh >> 2, h = bh & 3;

    #pragma unroll 1
    for (int pass = 0; pass < 2; pass++) {
        int qt = pass ? (SS / 64 - 1 - qp) : qp;
        int q0 = qt * 64;

        __syncthreads();
        #pragma unroll
        for (int it = 0; it < 4; it++) {
            int o = (tid + it * 256) * 4;
            float4 q = *(const float4*)&Qh[(size_t)q0 * 64 + o];
            q.x *= 0.125f; q.y *= 0.125f; q.z *= 0.125f; q.w *= 0.125f;
            *(float4*)&Qs[o] = q;
        }

        float m_i[4], l_i[4], acc[4][4];
        #pragma unroll
        for (int i = 0; i < 4; i++) {
            m_i[i] = -3.0e38f; l_i[i] = 0.f;
            #pragma unroll
            for (int j = 0; j < 4; j++) acc[i][j] = 0.f;
        }

        #pragma unroll 1
        for (int kt = 0; kt <= qt; kt++) {
            __syncthreads();
            #pragma unroll
            for (int it = 0; it < 4; it++) {
                int o = (tid + it * 256) * 4;
                *(float4*)&KPs[o] = *(const float4*)&Kh[(size_t)kt * 4096 + o];
                *(float4*)&Vs[o]  = *(const float4*)&Vh[(size_t)kt * 4096 + o];
            }
            __syncthreads();

            float sreg[4][4];
            #pragma unroll
            for (int i = 0; i < 4; i++)
                #pragma unroll
                for (int j = 0; j < 4; j++) sreg[i][j] = 0.f;

            for (int d = 0; d < 64; d += 4) {
                float4 qv[4], kv[4];
                #pragma unroll
                for (int i = 0; i < 4; i++) qv[i] = *(const float4*)&Qs[(ty * 4 + i) * 64 + d];
                #pragma unroll
                for (int j = 0; j < 4; j++) kv[j] = *(const float4*)&KPs[(tx * 4 + j) * 64 + d];
                #pragma unroll
                for (int i = 0; i < 4; i++)
                    #pragma unroll
                    for (int j = 0; j < 4; j++)
                        sreg[i][j] += qv[i].x * kv[j].x + qv[i].y * kv[j].y +
                                      qv[i].z * kv[j].z + qv[i].w * kv[j].w;
            }
            __syncthreads();

            if (kt == qt) {
                #pragma unroll
                for (int i = 0; i < 4; i++)
                    #pragma unroll
                    for (int j = 0; j < 4; j++)
                        if (ty * 4 + i < tx * 4 + j) sreg[i][j] = -3.0e38f;
            }

            #pragma unroll
            for (int i = 0; i < 4; i++) {
                float mx = fmaxf(fmaxf(sreg[i][0], sreg[i][1]),
                                 fmaxf(sreg[i][2], sreg[i][3]));
                #pragma unroll
                for (int off = 1; off < 16; off <<= 1)
                    mx = fmaxf(mx, __shfl_xor_sync(0xffffffffu, mx, off));
                float mnew = fmaxf(m_i[i], mx);
                float corr = __expf(m_i[i] - mnew);
                float rs = 0.f;
                #pragma unroll
                for (int j = 0; j < 4; j++) {
                    float p = __expf(sreg[i][j] - mnew);
                    sreg[i][j] = p;
                    rs += p;
                }
                #pragma unroll
                for (int off = 1; off < 16; off <<= 1)
                    rs += __shfl_xor_sync(0xffffffffu, rs, off);
                l_i[i] = l_i[i] * corr + rs;
                m_i[i] = mnew;
                #pragma unroll
                for (int j = 0; j < 4; j++) acc[i][j] *= corr;
            }

            #pragma unroll
            for (int i = 0; i < 4; i++)
                *(float4*)&KPs[(ty * 4 + i) * 64 + tx * 4] =
                    make_float4(sreg[i][0], sreg[i][1], sreg[i][2], sreg[i][3]);
            __syncthreads();

            #pragma unroll 4
            for (int jj = 0; jj < 64; jj++) {
                float4 v = *(const float4*)&Vs[jj * 64 + tx * 4];
                #pragma unroll
                for (int i = 0; i < 4; i++) {
                    float p = KPs[(ty * 4 + i) * 64 + jj];
                    acc[i][0] += p * v.x;
                    acc[i][1] += p * v.y;
                    acc[i][2] += p * v.z;
                    acc[i][3] += p * v.w;
                }
            }
        }

        #pragma unroll
        for (int i = 0; i < 4; i++) {
            float inv = 1.0f / l_i[i];
            int row = q0 + ty * 4 + i;
            float4 o = make_float4(acc[i][0] * inv, acc[i][1] * inv,
                                   acc[i][2] * inv, acc[i][3] * inv);
            size_t off = (((size_t)b * SS + row) << 8) + (size_t)(h << 6) + (size_t)(tx << 2);
            *(float4*)&g_AO[off] = o;
        }
    }
}

extern "C" void kernel_launch(void* const* d_in, const int* in_sizes, int n_in,
                              void* d_out, int out_size) {
    const float* q_in  = (const float*)d_in[0];
    const float* kv_in = (const float*)d_in[1];
    const float* Wq    = (const float*)d_in[3];
    const float* Wk    = (const float*)d_in[4];
    const float* Wv    = (const float*)d_in[5];
    const float* Wo    = (const float*)d_in[6];
    float* out = (float*)d_out;

    float *pQ, *pK, *pV, *pAO;
    cudaGetSymbolAddress((void**)&pQ,  g_Q);
    cudaGetSymbolAddress((void**)&pK,  g_K);
    cudaGetSymbolAddress((void**)&pV,  g_V);
    cudaGetSymbolAddress((void**)&pAO, g_AO);

    fold_wq_kernel<<<(INDIM * NKV + 255) / 256, 256>>>(Wq);

    dim3 gqkv(NKV / 64, (BB * SS) / 128, 3);   // (4, 32, 3) = 384 CTAs
    qkv_gemm_kernel<<<gqkv, 256>>>(q_in, kv_in, Wk, Wv, pQ, pK, pV);

    attn_kernel<<<dim3(SS / 128, BB * KVH_), 256>>>();   // (16, 8) paired

    out_gemm_kernel<<<dim3(INDIM / 64, (BB * SS) / 128), 256>>>(pAO, Wo, out);
}

// round 3
// speedup vs baseline: 5.3230x; 3.2472x over previous
#include <cuda_runtime.h>
#include <math.h>

#define BB      2
#define SS      2048
#define INDIM   1024
#define QH_     16
#define KVH_    4
#define HD_     64
#define G_      4
#define NKV     256

__device__ float g_Wqs[INDIM * NKV];
__device__ float g_Q[BB * KVH_ * SS * HD_];
__device__ float g_K[BB * KVH_ * SS * HD_];
__device__ float g_V[BB * KVH_ * SS * HD_];
__device__ float g_AO[BB * SS * NKV];

// --------------------------- small helpers --------------------------------
__device__ __forceinline__ unsigned f2tf(float f) {
    unsigned r;
    asm("cvt.rna.tf32.f32 %0, %1;" : "=r"(r) : "f"(f));
    return r;
}
__device__ __forceinline__ float ex2f(float x) {
    float y;
    asm("ex2.approx.f32 %0, %1;" : "=f"(y) : "f"(x));
    return y;
}
__device__ __forceinline__ void mma_tf32(float (&d)[4], const unsigned (&a)[4],
                                         const unsigned (&b)[2]) {
    asm volatile(
        "mma.sync.aligned.m16n8k8.row.col.f32.tf32.tf32.f32 "
        "{%0,%1,%2,%3}, {%4,%5,%6,%7}, {%8,%9}, {%0,%1,%2,%3};"
        : "+f"(d[0]), "+f"(d[1]), "+f"(d[2]), "+f"(d[3])
        : "r"(a[0]), "r"(a[1]), "r"(a[2]), "r"(a[3]), "r"(b[0]), "r"(b[1]));
}

// ---------------------------------------------------------------------------
// Fold Wq over group axis: Wq_sum[i,h,d] = sum_g Wq[i, h*G+g, d]
// ---------------------------------------------------------------------------
__global__ void fold_wq_kernel(const float* __restrict__ Wq) {
    int idx = blockIdx.x * blockDim.x + threadIdx.x;
    if (idx >= INDIM * NKV) return;
    int i = idx >> 8;
    int n = idx & 255;
    int h = n >> 6, d = n & 63;
    const float* p = Wq + (size_t)i * (QH_ * HD_) + (size_t)(h * G_) * HD_ + d;
    g_Wqs[idx] = p[0] + p[HD_] + p[2 * HD_] + p[3 * HD_];
}

// ---------------------------------------------------------------------------
// tf32 tensor-core GEMM: C[4096, N] = A[4096, KD] * B[KD, N]
// Block tile 128x64, BK=16, 256 threads = 8 warps (4m x 2n), warp tile 32x32.
// Double-buffered smem; operands rounded to tf32 at smem store.
// ---------------------------------------------------------------------------
template<int KD, int N, bool SCATTER>
__device__ __forceinline__ void gemm_body(
        const float* __restrict__ A, const float* __restrict__ Bm,
        float* __restrict__ C) {
    __shared__ unsigned As[2][16][136];   // [k][m], pad 136 -> conflict-free frags
    __shared__ unsigned Bs[2][16][72];    // [k][n], pad 72

    int tid = threadIdx.x;
    int w = tid >> 5, lane = tid & 31;
    int g = lane >> 2, qd = lane & 3;
    int wm = w & 3, wn = w >> 2;
    int m0 = blockIdx.y * 128, n0 = blockIdx.x * 64;

    int la_r = tid >> 2;            // 0..63
    int la_c = (tid & 3) << 2;      // 0,4,8,12
    int lb_r = tid >> 4;            // 0..15
    int lb_c = (tid & 15) << 2;     // 0..60

    const float* Ap = A + (size_t)(m0 + la_r) * KD + la_c;
    const float* Bp = Bm + (size_t)lb_r * N + n0 + lb_c;

    float acc[2][4][4];
    #pragma unroll
    for (int mt = 0; mt < 2; mt++)
        #pragma unroll
        for (int nt = 0; nt < 4; nt++)
            #pragma unroll
            for (int e = 0; e < 4; e++) acc[mt][nt][e] = 0.f;

    // prologue -> buf 0
    {
        float4 a0 = *(const float4*)(Ap);
        float4 a1 = *(const float4*)(Ap + (size_t)64 * KD);
        float4 b4 = *(const float4*)(Bp);
        #pragma unroll
        for (int j = 0; j < 4; j++) {
            As[0][la_c + j][la_r]      = f2tf(((const float*)&a0)[j]);
            As[0][la_c + j][la_r + 64] = f2tf(((const float*)&a1)[j]);
        }
        Bs[0][lb_r][lb_c + 0] = f2tf(b4.x);
        Bs[0][lb_r][lb_c + 1] = f2tf(b4.y);
        Bs[0][lb_r][lb_c + 2] = f2tf(b4.z);
        Bs[0][lb_r][lb_c + 3] = f2tf(b4.w);
    }
    __syncthreads();

    const int KT = KD / 16;
    int buf = 0;
    #pragma unroll 1
    for (int t = 0; t < KT; t++) {
        bool more = (t + 1 < KT);
        float4 na0, na1, nb4;
        if (more) {
            int k0 = (t + 1) * 16;
            na0 = *(const float4*)(Ap + k0);
            na1 = *(const float4*)(Ap + (size_t)64 * KD + k0);
            nb4 = *(const float4*)(Bp + (size_t)k0 * N);
        }
        #pragma unroll
        for (int ks = 0; ks < 2; ks++) {
            int kb = ks * 8;
            unsigned af[2][4];
            #pragma unroll
            for (int mt = 0; mt < 2; mt++) {
                int row = wm * 32 + mt * 16 + g;
                af[mt][0] = As[buf][kb + qd][row];
                af[mt][1] = As[buf][kb + qd][row + 8];
                af[mt][2] = As[buf][kb + qd + 4][row];
                af[mt][3] = As[buf][kb + qd + 4][row + 8];
            }
            unsigned bf[4][2];
            #pragma unroll
            for (int nt = 0; nt < 4; nt++) {
                int col = wn * 32 + nt * 8 + g;
                bf[nt][0] = Bs[buf][kb + qd][col];
                bf[nt][1] = Bs[buf][kb + qd + 4][col];
            }
            #pragma unroll
            for (int mt = 0; mt < 2; mt++)
                #pragma unroll
                for (int nt = 0; nt < 4; nt++)
                    mma_tf32(acc[mt][nt], af[mt], bf[nt]);
        }
        if (more) {
            int nb = buf ^ 1;
            #pragma unroll
            for (int j = 0; j < 4; j++) {
                As[nb][la_c + j][la_r]      = f2tf(((const float*)&na0)[j]);
                As[nb][la_c + j][la_r + 64] = f2tf(((const float*)&na1)[j]);
            }
            Bs[nb][lb_r][lb_c + 0] = f2tf(nb4.x);
            Bs[nb][lb_r][lb_c + 1] = f2tf(nb4.y);
            Bs[nb][lb_r][lb_c + 2] = f2tf(nb4.z);
            Bs[nb][lb_r][lb_c + 3] = f2tf(nb4.w);
        }
        __syncthreads();
        buf ^= 1;
    }

    #pragma unroll
    for (int mt = 0; mt < 2; mt++) {
        #pragma unroll
        for (int nt = 0; nt < 4; nt++) {
            int row = m0 + wm * 32 + mt * 16 + g;
            int col = n0 + wn * 32 + nt * 8 + 2 * qd;
            float2 lo = make_float2(acc[mt][nt][0], acc[mt][nt][1]);
            float2 hi = make_float2(acc[mt][nt][2], acc[mt][nt][3]);
            if (SCATTER) {
                int b = row >> 11, s = row & 2047;
                int h = col >> 6, d = col & 63;
                size_t base = (((size_t)(b * KVH_ + h) * SS) << 6) + (size_t)d;
                *(float2*)&C[base + ((size_t)s << 6)]       = lo;
                *(float2*)&C[base + ((size_t)(s + 8) << 6)] = hi;
            } else {
                *(float2*)&C[(size_t)row * N + col]       = lo;
                *(float2*)&C[(size_t)(row + 8) * N + col] = hi;
            }
        }
    }
}

__global__ void __launch_bounds__(256) qkv_gemm_kernel(
        const float* __restrict__ q_in, const float* __restrict__ kv_in,
        const float* __restrict__ Wk, const float* __restrict__ Wv,
        float* __restrict__ Q, float* __restrict__ K, float* __restrict__ V) {
    int z = blockIdx.z;
    const float* A  = (z == 0) ? q_in : kv_in;
    const float* Bm = (z == 0) ? g_Wqs : ((z == 1) ? Wk : Wv);
    float* C        = (z == 0) ? Q : ((z == 1) ? K : V);
    gemm_body<INDIM, NKV, true>(A, Bm, C);
}

__global__ void __launch_bounds__(256) out_gemm_kernel(
        const float* __restrict__ A, const float* __restrict__ Bm,
        float* __restrict__ C) {
    gemm_body<NKV, INDIM, false>(A, Bm, C);
}

// ---------------------------------------------------------------------------
// Causal flash attention with tf32 tensor cores.
// 128 threads = 4 warps; CTA tile 64 Q x 64 K; warp = 16 Q rows.
// Q fragments live in registers; P is staged through smem (aliases Ks).
// CTA handles q-tiles qp and 31-qp -> perfectly balanced 33 KV tiles.
// Softmax in exp2 domain: scale (1/8)*log2(e) folded into Q.
// ---------------------------------------------------------------------------
#define QSCALE 0.180336879f   // 0.125 * log2(e)

__global__ void __launch_bounds__(128) attn_kernel() {
    __shared__ unsigned Ks[64][68];   // K tile [key][dim]; aliased: Q stage, P tile
    __shared__ unsigned Vs[64][72];   // V tile [key][dim]

    int bh = blockIdx.y;
    int qp = blockIdx.x;              // 0..15
    const float* Qh = g_Q + (size_t)bh * SS * HD_;
    const float* Kh = g_K + (size_t)bh * SS * HD_;
    const float* Vh = g_V + (size_t)bh * SS * HD_;

    int tid = threadIdx.x;
    int w = tid >> 5, lane = tid & 31;
    int g = lane >> 2, qd = lane & 3;
    int r0 = w * 16 + g;              // local Q row (and +8)
    int b = bh >> 2, h = bh & 3;

    int lr = tid >> 4;                // 0..7  (tile loader)
    int lc = tid & 15;                // 0..15

    #pragma unroll 1
    for (int pass = 0; pass < 2; pass++) {
        int qt = pass ? (31 - qp) : qp;
        int q0 = qt * 64;

        __syncthreads();
        // stage Q into Ks (scaled + tf32), then pull fragments to registers
        {
            const float4* Qsrc = (const float4*)(Qh + (size_t)q0 * 64);
            #pragma unroll
            for (int it = 0; it < 8; it++) {
                int r = lr + it * 8;
                float4 q = Qsrc[r * 16 + lc];
                uint4 u;
                u.x = f2tf(q.x * QSCALE); u.y = f2tf(q.y * QSCALE);
                u.z = f2tf(q.z * QSCALE); u.w = f2tf(q.w * QSCALE);
                *(uint4*)&Ks[r][lc * 4] = u;
            }
        }
        __syncthreads();

        unsigned qf[8][4];
        #pragma unroll
        for (int kt2 = 0; kt2 < 8; kt2++) {
            qf[kt2][0] = Ks[r0][kt2 * 8 + qd];
            qf[kt2][1] = Ks[r0 + 8][kt2 * 8 + qd];
            qf[kt2][2] = Ks[r0][kt2 * 8 + qd + 4];
            qf[kt2][3] = Ks[r0 + 8][kt2 * 8 + qd + 4];
        }

        float m0 = -3.0e38f, m1 = -3.0e38f, l0 = 0.f, l1 = 0.f;
        float oacc[8][4];
        #pragma unroll
        for (int dt = 0; dt < 8; dt++)
            #pragma unroll
            for (int e = 0; e < 4; e++) oacc[dt][e] = 0.f;

        #pragma unroll 1
        for (int kt = 0; kt <= qt; kt++) {
            __syncthreads();    // qf reads / previous Ps,Vs reads complete
            {
                const float4* Ksrc = (const float4*)(Kh + (size_t)kt * 4096);
                const float4* Vsrc = (const float4*)(Vh + (size_t)kt * 4096);
                #pragma unroll
                for (int it = 0; it < 8; it++) {
                    int r = lr + it * 8;
                    float4 kv = Ksrc[r * 16 + lc];
                    float4 vv = Vsrc[r * 16 + lc];
                    uint4 ku, vu;
                    ku.x = f2tf(kv.x); ku.y = f2tf(kv.y);
                    ku.z = f2tf(kv.z); ku.w = f2tf(kv.w);
                    vu.x = f2tf(vv.x); vu.y = f2tf(vv.y);
                    vu.z = f2tf(vv.z); vu.w = f2tf(vv.w);
                    *(uint4*)&Ks[r][lc * 4] = ku;
                    *(uint4*)&Vs[r][lc * 4] = vu;
                }
            }
            __syncthreads();

            // --- S = Q K^T (16x64 per warp) ---
            float sacc[8][4];
            #pragma unroll
            for (int nt = 0; nt < 8; nt++)
                #pragma unroll
                for (int e = 0; e < 4; e++) sacc[nt][e] = 0.f;

            #pragma unroll
            for (int nt = 0; nt < 8; nt++) {
                #pragma unroll
                for (int ks = 0; ks < 8; ks++) {
                    unsigned kb[2];
                    kb[0] = Ks[nt * 8 + g][ks * 8 + qd];
                    kb[1] = Ks[nt * 8 + g][ks * 8 + qd + 4];
                    mma_tf32(sacc[nt], qf[ks], kb);
                }
            }

            if (kt == qt) {   // causal mask on diagonal tile
                int grow0 = q0 + r0;
                #pragma unroll
                for (int nt = 0; nt < 8; nt++) {
                    int col = kt * 64 + nt * 8 + 2 * qd;
                    if (col     > grow0)     sacc[nt][0] = -1.0e30f;
                    if (col + 1 > grow0)     sacc[nt][1] = -1.0e30f;
                    if (col     > grow0 + 8) sacc[nt][2] = -1.0e30f;
                    if (col + 1 > grow0 + 8) sacc[nt][3] = -1.0e30f;
                }
            }

            // --- online softmax (exp2 domain) ---
            float mx0 = -3.0e38f, mx1 = -3.0e38f;
            #pragma unroll
            for (int nt = 0; nt < 8; nt++) {
                mx0 = fmaxf(mx0, fmaxf(sacc[nt][0], sacc[nt][1]));
                mx1 = fmaxf(mx1, fmaxf(sacc[nt][2], sacc[nt][3]));
            }
            mx0 = fmaxf(mx0, __shfl_xor_sync(0xffffffffu, mx0, 1));
            mx0 = fmaxf(mx0, __shfl_xor_sync(0xffffffffu, mx0, 2));
            mx1 = fmaxf(mx1, __shfl_xor_sync(0xffffffffu, mx1, 1));
            mx1 = fmaxf(mx1, __shfl_xor_sync(0xffffffffu, mx1, 2));
            float mn0 = fmaxf(m0, mx0), mn1 = fmaxf(m1, mx1);
            float c0 = ex2f(m0 - mn0), c1 = ex2f(m1 - mn1);
            m0 = mn0; m1 = mn1;

            float rs0 = 0.f, rs1 = 0.f;
            #pragma unroll
            for (int nt = 0; nt < 8; nt++) {
                float p0 = ex2f(sacc[nt][0] - mn0);
                float p1 = ex2f(sacc[nt][1] - mn0);
                float p2 = ex2f(sacc[nt][2] - mn1);
                float p3 = ex2f(sacc[nt][3] - mn1);
                sacc[nt][0] = p0; sacc[nt][1] = p1;
                sacc[nt][2] = p2; sacc[nt][3] = p3;
                rs0 += p0 + p1; rs1 += p2 + p3;
            }
            rs0 += __shfl_xor_sync(0xffffffffu, rs0, 1);
            rs0 += __shfl_xor_sync(0xffffffffu, rs0, 2);
            rs1 += __shfl_xor_sync(0xffffffffu, rs1, 1);
            rs1 += __shfl_xor_sync(0xffffffffu, rs1, 2);
            l0 = l0 * c0 + rs0;
            l1 = l1 * c1 + rs1;
            #pragma unroll
            for (int dt = 0; dt < 8; dt++) {
                oacc[dt][0] *= c0; oacc[dt][1] *= c0;
                oacc[dt][2] *= c1; oacc[dt][3] *= c1;
            }

            // --- P -> smem (aliases Ks; all K reads are complete) ---
            __syncthreads();
            #pragma unroll
            for (int nt = 0; nt < 8; nt++) {
                uint2 u0, u1;
                u0.x = f2tf(sacc[nt][0]); u0.y = f2tf(sacc[nt][1]);
                u1.x = f2tf(sacc[nt][2]); u1.y = f2tf(sacc[nt][3]);
                *(uint2*)&Ks[r0][nt * 8 + 2 * qd]     = u0;
                *(uint2*)&Ks[r0 + 8][nt * 8 + 2 * qd] = u1;
            }
            __syncwarp();   // each warp reads back only its own rows

            unsigned pa[8][4];
            #pragma unroll
            for (int ks = 0; ks < 8; ks++) {
                pa[ks][0] = Ks[r0][ks * 8 + qd];
                pa[ks][1] = Ks[r0 + 8][ks * 8 + qd];
                pa[ks][2] = Ks[r0][ks * 8 + qd + 4];
                pa[ks][3] = Ks[r0 + 8][ks * 8 + qd + 4];
            }
            #pragma unroll
            for (int dt = 0; dt < 8; dt++) {
                #pragma unroll
                for (int ks = 0; ks < 8; ks++) {
                    unsigned vb[2];
                    vb[0] = Vs[ks * 8 + qd][dt * 8 + g];
                    vb[1] = Vs[ks * 8 + qd + 4][dt * 8 + g];
                    mma_tf32(oacc[dt], pa[ks], vb);
                }
            }
        }

        // --- epilogue: normalize, write [b][s][h*64+d] ---
        float il0 = 1.0f / l0, il1 = 1.0f / l1;
        int grow = q0 + r0;
        size_t base0 = (((size_t)b * SS + grow) << 8) + (size_t)(h << 6);
        size_t base1 = (((size_t)b * SS + grow + 8) << 8) + (size_t)(h << 6);
        #pragma unroll
        for (int dt = 0; dt < 8; dt++) {
            int d = dt * 8 + 2 * qd;
            *(float2*)&g_AO[base0 + d] =
                make_float2(oacc[dt][0] * il0, oacc[dt][1] * il0);
            *(float2*)&g_AO[base1 + d] =
                make_float2(oacc[dt][2] * il1, oacc[dt][3] * il1);
        }
    }
}

extern "C" void kernel_launch(void* const* d_in, const int* in_sizes, int n_in,
                              void* d_out, int out_size) {
    const float* q_in  = (const float*)d_in[0];
    const float* kv_in = (const float*)d_in[1];
    const float* Wq    = (const float*)d_in[3];
    const float* Wk    = (const float*)d_in[4];
    const float* Wv    = (const float*)d_in[5];
    const float* Wo    = (const float*)d_in[6];
    float* out = (float*)d_out;

    float *pQ, *pK, *pV, *pAO;
    cudaGetSymbolAddress((void**)&pQ,  g_Q);
    cudaGetSymbolAddress((void**)&pK,  g_K);
    cudaGetSymbolAddress((void**)&pV,  g_V);
    cudaGetSymbolAddress((void**)&pAO, g_AO);

    fold_wq_kernel<<<(INDIM * NKV + 255) / 256, 256>>>(Wq);

    dim3 gqkv(NKV / 64, (BB * SS) / 128, 3);   // (4, 32, 3)
    qkv_gemm_kernel<<<gqkv, 256>>>(q_in, kv_in, Wk, Wv, pQ, pK, pV);

    attn_kernel<<<dim3(16, BB * KVH_), 128>>>();

    out_gemm_kernel<<<dim3(INDIM / 64, (BB * SS) / 128), 256>>>(pAO, Wo, out);
}

// round 4
// speedup vs baseline: 5.3791x; 1.0105x over previous
#include <cuda_runtime.h>
#include <math.h>

#define BB      2
#define SS      2048
#define INDIM   1024
#define QH_     16
#define KVH_    4
#define HD_     64
#define G_      4
#define NKV     256

__device__ float g_Wqs[INDIM * NKV];
__device__ float g_Q[BB * KVH_ * SS * HD_];
__device__ float g_K[BB * KVH_ * SS * HD_];
__device__ float g_V[BB * KVH_ * SS * HD_];
__device__ float g_AO[BB * SS * NKV];

// --------------------------- small helpers --------------------------------
__device__ __forceinline__ unsigned f2tf(float f) {
    unsigned r;
    asm("cvt.rna.tf32.f32 %0, %1;" : "=r"(r) : "f"(f));
    return r;
}
__device__ __forceinline__ float ex2f(float x) {
    float y;
    asm("ex2.approx.f32 %0, %1;" : "=f"(y) : "f"(x));
    return y;
}
__device__ __forceinline__ void mma_tf32(float (&d)[4], const unsigned (&a)[4],
                                         const unsigned (&b)[2]) {
    asm volatile(
        "mma.sync.aligned.m16n8k8.row.col.f32.tf32.tf32.f32 "
        "{%0,%1,%2,%3}, {%4,%5,%6,%7}, {%8,%9}, {%0,%1,%2,%3};"
        : "+f"(d[0]), "+f"(d[1]), "+f"(d[2]), "+f"(d[3])
        : "r"(a[0]), "r"(a[1]), "r"(a[2]), "r"(a[3]), "r"(b[0]), "r"(b[1]));
}

// ---------------------------------------------------------------------------
// Fold Wq over group axis: Wq_sum[i,h,d] = sum_g Wq[i, h*G+g, d]
// ---------------------------------------------------------------------------
__global__ void fold_wq_kernel(const float* __restrict__ Wq) {
    int idx = blockIdx.x * blockDim.x + threadIdx.x;
    if (idx >= INDIM * NKV) return;
    int i = idx >> 8;
    int n = idx & 255;
    int h = n >> 6, d = n & 63;
    const float* p = Wq + (size_t)i * (QH_ * HD_) + (size_t)(h * G_) * HD_ + d;
    g_Wqs[idx] = p[0] + p[HD_] + p[2 * HD_] + p[3 * HD_];
}

// ---------------------------------------------------------------------------
// tf32 tensor-core GEMM: C[4096, N] = A[4096, KD] * B[KD, N]
// Block tile 128x64, BK=16, 256 threads = 8 warps (4m x 2n), warp tile 32x32.
// Double-buffered smem; operands rounded to tf32 at smem store.
// ---------------------------------------------------------------------------
template<int KD, int N, bool SCATTER>
__device__ __forceinline__ void gemm_body(
        const float* __restrict__ A, const float* __restrict__ Bm,
        float* __restrict__ C) {
    __shared__ unsigned As[2][16][136];   // [k][m], pad 136 -> conflict-free frags
    __shared__ unsigned Bs[2][16][72];    // [k][n], pad 72

    int tid = threadIdx.x;
    int w = tid >> 5, lane = tid & 31;
    int g = lane >> 2, qd = lane & 3;
    int wm = w & 3, wn = w >> 2;
    int m0 = blockIdx.y * 128, n0 = blockIdx.x * 64;

    int la_r = tid >> 2;            // 0..63
    int la_c = (tid & 3) << 2;      // 0,4,8,12
    int lb_r = tid >> 4;            // 0..15
    int lb_c = (tid & 15) << 2;     // 0..60

    const float* Ap = A + (size_t)(m0 + la_r) * KD + la_c;
    const float* Bp = Bm + (size_t)lb_r * N + n0 + lb_c;

    float acc[2][4][4];
    #pragma unroll
    for (int mt = 0; mt < 2; mt++)
        #pragma unroll
        for (int nt = 0; nt < 4; nt++)
            #pragma unroll
            for (int e = 0; e < 4; e++) acc[mt][nt][e] = 0.f;

    // prologue -> buf 0
    {
        float4 a0 = *(const float4*)(Ap);
        float4 a1 = *(const float4*)(Ap + (size_t)64 * KD);
        float4 b4 = *(const float4*)(Bp);
        #pragma unroll
        for (int j = 0; j < 4; j++) {
            As[0][la_c + j][la_r]      = f2tf(((const float*)&a0)[j]);
            As[0][la_c + j][la_r + 64] = f2tf(((const float*)&a1)[j]);
        }
        Bs[0][lb_r][lb_c + 0] = f2tf(b4.x);
        Bs[0][lb_r][lb_c + 1] = f2tf(b4.y);
        Bs[0][lb_r][lb_c + 2] = f2tf(b4.z);
        Bs[0][lb_r][lb_c + 3] = f2tf(b4.w);
    }
    __syncthreads();

    const int KT = KD / 16;
    int buf = 0;
    #pragma unroll 1
    for (int t = 0; t < KT; t++) {
        bool more = (t + 1 < KT);
        float4 na0, na1, nb4;
        if (more) {
            int k0 = (t + 1) * 16;
            na0 = *(const float4*)(Ap + k0);
            na1 = *(const float4*)(Ap + (size_t)64 * KD + k0);
            nb4 = *(const float4*)(Bp + (size_t)k0 * N);
        }
        #pragma unroll
        for (int ks = 0; ks < 2; ks++) {
            int kb = ks * 8;
            unsigned af[2][4];
            #pragma unroll
            for (int mt = 0; mt < 2; mt++) {
                int row = wm * 32 + mt * 16 + g;
                af[mt][0] = As[buf][kb + qd][row];
                af[mt][1] = As[buf][kb + qd][row + 8];
                af[mt][2] = As[buf][kb + qd + 4][row];
                af[mt][3] = As[buf][kb + qd + 4][row + 8];
            }
            unsigned bf[4][2];
            #pragma unroll
            for (int nt = 0; nt < 4; nt++) {
                int col = wn * 32 + nt * 8 + g;
                bf[nt][0] = Bs[buf][kb + qd][col];
                bf[nt][1] = Bs[buf][kb + qd + 4][col];
            }
            #pragma unroll
            for (int mt = 0; mt < 2; mt++)
                #pragma unroll
                for (int nt = 0; nt < 4; nt++)
                    mma_tf32(acc[mt][nt], af[mt], bf[nt]);
        }
        if (more) {
            int nb = buf ^ 1;
            #pragma unroll
            for (int j = 0; j < 4; j++) {
                As[nb][la_c + j][la_r]      = f2tf(((const float*)&na0)[j]);
                As[nb][la_c + j][la_r + 64] = f2tf(((const float*)&na1)[j]);
            }
            Bs[nb][lb_r][lb_c + 0] = f2tf(nb4.x);
            Bs[nb][lb_r][lb_c + 1] = f2tf(nb4.y);
            Bs[nb][lb_r][lb_c + 2] = f2tf(nb4.z);
            Bs[nb][lb_r][lb_c + 3] = f2tf(nb4.w);
        }
        __syncthreads();
        buf ^= 1;
    }

    #pragma unroll
    for (int mt = 0; mt < 2; mt++) {
        #pragma unroll
        for (int nt = 0; nt < 4; nt++) {
            int row = m0 + wm * 32 + mt * 16 + g;
            int col = n0 + wn * 32 + nt * 8 + 2 * qd;
            float2 lo = make_float2(acc[mt][nt][0], acc[mt][nt][1]);
            float2 hi = make_float2(acc[mt][nt][2], acc[mt][nt][3]);
            if (SCATTER) {
                int b = row >> 11, s = row & 2047;
                int h = col >> 6, d = col & 63;
                size_t base = (((size_t)(b * KVH_ + h) * SS) << 6) + (size_t)d;
                *(float2*)&C[base + ((size_t)s << 6)]       = lo;
                *(float2*)&C[base + ((size_t)(s + 8) << 6)] = hi;
            } else {
                *(float2*)&C[(size_t)row * N + col]       = lo;
                *(float2*)&C[(size_t)(row + 8) * N + col] = hi;
            }
        }
    }
}

__global__ void __launch_bounds__(256) qkv_gemm_kernel(
        const float* __restrict__ q_in, const float* __restrict__ kv_in,
        const float* __restrict__ Wk, const float* __restrict__ Wv,
        float* __restrict__ Q, float* __restrict__ K, float* __restrict__ V) {
    int z = blockIdx.z;
    const float* A  = (z == 0) ? q_in : kv_in;
    const float* Bm = (z == 0) ? g_Wqs : ((z == 1) ? Wk : Wv);
    float* C        = (z == 0) ? Q : ((z == 1) ? K : V);
    gemm_body<INDIM, NKV, true>(A, Bm, C);
}

__global__ void __launch_bounds__(256) out_gemm_kernel(
        const float* __restrict__ A, const float* __restrict__ Bm,
        float* __restrict__ C) {
    gemm_body<NKV, INDIM, false>(A, Bm, C);
}

// ---------------------------------------------------------------------------
// Causal flash attention with tf32 tensor cores.
// 128 threads = 4 warps; CTA tile 64 Q x 64 K; warp = 16 Q rows.
// Q fragments live in registers; P is staged through smem (aliases Ks).
// CTA handles q-tiles qp and 31-qp -> perfectly balanced 33 KV tiles.
// Softmax in exp2 domain: scale (1/8)*log2(e) folded into Q.
// ---------------------------------------------------------------------------
#define QSCALE 0.180336879f   // 0.125 * log2(e)

__global__ void __launch_bounds__(128) attn_kernel() {
    __shared__ unsigned Ks[64][68];   // K tile [key][dim]; aliased: Q stage, P tile
    __shared__ unsigned Vs[64][72];   // V tile [key][dim]

    int bh = blockIdx.y;
    int qp = blockIdx.x;              // 0..15
    const float* Qh = g_Q + (size_t)bh * SS * HD_;
    const float* Kh = g_K + (size_t)bh * SS * HD_;
    const float* Vh = g_V + (size_t)bh * SS * HD_;

    int tid = threadIdx.x;
    int w = tid >> 5, lane = tid & 31;
    int g = lane >> 2, qd = lane & 3;
    int r0 = w * 16 + g;              // local Q row (and +8)
    int b = bh >> 2, h = bh & 3;

    int lr = tid >> 4;                // 0..7  (tile loader)
    int lc = tid & 15;                // 0..15

    #pragma unroll 1
    for (int pass = 0; pass < 2; pass++) {
        int qt = pass ? (31 - qp) : qp;
        int q0 = qt * 64;

        __syncthreads();
        // stage Q into Ks (scaled + tf32), then pull fragments to registers
        {
            const float4* Qsrc = (const float4*)(Qh + (size_t)q0 * 64);
            #pragma unroll
            for (int it = 0; it < 8; it++) {
                int r = lr + it * 8;
                float4 q = Qsrc[r * 16 + lc];
                uint4 u;
                u.x = f2tf(q.x * QSCALE); u.y = f2tf(q.y * QSCALE);
                u.z = f2tf(q.z * QSCALE); u.w = f2tf(q.w * QSCALE);
                *(uint4*)&Ks[r][lc * 4] = u;
            }
        }
        __syncthreads();

        unsigned qf[8][4];
        #pragma unroll
        for (int kt2 = 0; kt2 < 8; kt2++) {
            qf[kt2][0] = Ks[r0][kt2 * 8 + qd];
            qf[kt2][1] = Ks[r0 + 8][kt2 * 8 + qd];
            qf[kt2][2] = Ks[r0][kt2 * 8 + qd + 4];
            qf[kt2][3] = Ks[r0 + 8][kt2 * 8 + qd + 4];
        }

        float m0 = -3.0e38f, m1 = -3.0e38f, l0 = 0.f, l1 = 0.f;
        float oacc[8][4];
        #pragma unroll
        for (int dt = 0; dt < 8; dt++)
            #pragma unroll
            for (int e = 0; e < 4; e++) oacc[dt][e] = 0.f;

        #pragma unroll 1
        for (int kt = 0; kt <= qt; kt++) {
            __syncthreads();    // qf reads / previous Ps,Vs reads complete
            {
                const float4* Ksrc = (const float4*)(Kh + (size_t)kt * 4096);
                const float4* Vsrc = (const float4*)(Vh + (size_t)kt * 4096);
                #pragma unroll
                for (int it = 0; it < 8; it++) {
                    int r = lr + it * 8;
                    float4 kv = Ksrc[r * 16 + lc];
                    float4 vv = Vsrc[r * 16 + lc];
                    uint4 ku, vu;
                    ku.x = f2tf(kv.x); ku.y = f2tf(kv.y);
                    ku.z = f2tf(kv.z); ku.w = f2tf(kv.w);
                    vu.x = f2tf(vv.x); vu.y = f2tf(vv.y);
                    vu.z = f2tf(vv.z); vu.w = f2tf(vv.w);
                    *(uint4*)&Ks[r][lc * 4] = ku;
                    *(uint4*)&Vs[r][lc * 4] = vu;
                }
            }
            __syncthreads();

            // --- S = Q K^T (16x64 per warp) ---
            float sacc[8][4];
            #pragma unroll
            for (int nt = 0; nt < 8; nt++)
                #pragma unroll
                for (int e = 0; e < 4; e++) sacc[nt][e] = 0.f;

            #pragma unroll
            for (int nt = 0; nt < 8; nt++) {
                #pragma unroll
                for (int ks = 0; ks < 8; ks++) {
                    unsigned kb[2];
                    kb[0] = Ks[nt * 8 + g][ks * 8 + qd];
                    kb[1] = Ks[nt * 8 + g][ks * 8 + qd + 4];
                    mma_tf32(sacc[nt], qf[ks], kb);
                }
            }

            if (kt == qt) {   // causal mask on diagonal tile
                int grow0 = q0 + r0;
                #pragma unroll
                for (int nt = 0; nt < 8; nt++) {
                    int col = kt * 64 + nt * 8 + 2 * qd;
                    if (col     > grow0)     sacc[nt][0] = -1.0e30f;
                    if (col + 1 > grow0)     sacc[nt][1] = -1.0e30f;
                    if (col     > grow0 + 8) sacc[nt][2] = -1.0e30f;
                    if (col + 1 > grow0 + 8) sacc[nt][3] = -1.0e30f;
                }
            }

            // --- online softmax (exp2 domain) ---
            float mx0 = -3.0e38f, mx1 = -3.0e38f;
            #pragma unroll
            for (int nt = 0; nt < 8; nt++) {
                mx0 = fmaxf(mx0, fmaxf(sacc[nt][0], sacc[nt][1]));
                mx1 = fmaxf(mx1, fmaxf(sacc[nt][2], sacc[nt][3]));
            }
            mx0 = fmaxf(mx0, __shfl_xor_sync(0xffffffffu, mx0, 1));
            mx0 = fmaxf(mx0, __shfl_xor_sync(0xffffffffu, mx0, 2));
            mx1 = fmaxf(mx1, __shfl_xor_sync(0xffffffffu, mx1, 1));
            mx1 = fmaxf(mx1, __shfl_xor_sync(0xffffffffu, mx1, 2));
            float mn0 = fmaxf(m0, mx0), mn1 = fmaxf(m1, mx1);
            float c0 = ex2f(m0 - mn0), c1 = ex2f(m1 - mn1);
            m0 = mn0; m1 = mn1;

            float rs0 = 0.f, rs1 = 0.f;
            #pragma unroll
            for (int nt = 0; nt < 8; nt++) {
                float p0 = ex2f(sacc[nt][0] - mn0);
                float p1 = ex2f(sacc[nt][1] - mn0);
                float p2 = ex2f(sacc[nt][2] - mn1);
                float p3 = ex2f(sacc[nt][3] - mn1);
                sacc[nt][0] = p0; sacc[nt][1] = p1;
                sacc[nt][2] = p2; sacc[nt][3] = p3;
                rs0 += p0 + p1; rs1 += p2 + p3;
            }
            rs0 += __shfl_xor_sync(0xffffffffu, rs0, 1);
            rs0 += __shfl_xor_sync(0xffffffffu, rs0, 2);
            rs1 += __shfl_xor_sync(0xffffffffu, rs1, 1);
            rs1 += __shfl_xor_sync(0xffffffffu, rs1, 2);
            l0 = l0 * c0 + rs0;
            l1 = l1 * c1 + rs1;
            #pragma unroll
            for (int dt = 0; dt < 8; dt++) {
                oacc[dt][0] *= c0; oacc[dt][1] *= c0;
                oacc[dt][2] *= c1; oacc[dt][3] *= c1;
            }

            // --- P -> smem (aliases Ks; all K reads are complete) ---
            __syncthreads();
            #pragma unroll
            for (int nt = 0; nt < 8; nt++) {
                uint2 u0, u1;
                u0.x = f2tf(sacc[nt][0]); u0.y = f2tf(sacc[nt][1]);
                u1.x = f2tf(sacc[nt][2]); u1.y = f2tf(sacc[nt][3]);
                *(uint2*)&Ks[r0][nt * 8 + 2 * qd]     = u0;
                *(uint2*)&Ks[r0 + 8][nt * 8 + 2 * qd] = u1;
            }
            __syncwarp();   // each warp reads back only its own rows

            unsigned pa[8][4];
            #pragma unroll
            for (int ks = 0; ks < 8; ks++) {
                pa[ks][0] = Ks[r0][ks * 8 + qd];
                pa[ks][1] = Ks[r0 + 8][ks * 8 + qd];
                pa[ks][2] = Ks[r0][ks * 8 + qd + 4];
                pa[ks][3] = Ks[r0 + 8][ks * 8 + qd + 4];
            }
            #pragma unroll
            for (int dt = 0; dt < 8; dt++) {
                #pragma unroll
                for (int ks = 0; ks < 8; ks++) {
                    unsigned vb[2];
                    vb[0] = Vs[ks * 8 + qd][dt * 8 + g];
                    vb[1] = Vs[ks * 8 + qd + 4][dt * 8 + g];
                    mma_tf32(oacc[dt], pa[ks], vb);
                }
            }
        }

        // --- epilogue: normalize, write [b][s][h*64+d] ---
        float il0 = 1.0f / l0, il1 = 1.0f / l1;
        int grow = q0 + r0;
        size_t base0 = (((size_t)b * SS + grow) << 8) + (size_t)(h << 6);
        size_t base1 = (((size_t)b * SS + grow + 8) << 8) + (size_t)(h << 6);
        #pragma unroll
        for (int dt = 0; dt < 8; dt++) {
            int d = dt * 8 + 2 * qd;
            *(float2*)&g_AO[base0 + d] =
                make_float2(oacc[dt][0] * il0, oacc[dt][1] * il0);
            *(float2*)&g_AO[base1 + d] =
                make_float2(oacc[dt][2] * il1, oacc[dt][3] * il1);
        }
    }
}

extern "C" void kernel_launch(void* const* d_in, const int* in_sizes, int n_in,
                              void* d_out, int out_size) {
    const float* q_in  = (const float*)d_in[0];
    const float* kv_in = (const float*)d_in[1];
    const float* Wq    = (const float*)d_in[3];
    const float* Wk    = (const float*)d_in[4];
    const float* Wv    = (const float*)d_in[5];
    const float* Wo    = (const float*)d_in[6];
    float* out = (float*)d_out;

    float *pQ, *pK, *pV, *pAO;
    cudaGetSymbolAddress((void**)&pQ,  g_Q);
    cudaGetSymbolAddress((void**)&pK,  g_K);
    cudaGetSymbolAddress((void**)&pV,  g_V);
    cudaGetSymbolAddress((void**)&pAO, g_AO);

    fold_wq_kernel<<<(INDIM * NKV + 255) / 256, 256>>>(Wq);

    dim3 gqkv(NKV / 64, (BB * SS) / 128, 3);   // (4, 32, 3)
    qkv_gemm_kernel<<<gqkv, 256>>>(q_in, kv_in, Wk, Wv, pQ, pK, pV);

    attn_kernel<<<dim3(16, BB * KVH_), 128>>>();

    out_gemm_kernel<<<dim3(INDIM / 64, (BB * SS) / 128), 256>>>(pAO, Wo, out);
}

// round 5
// speedup vs baseline: 5.4421x; 1.0117x over previous
#include <cuda_runtime.h>
#include <math.h>

#define BB      2
#define SS      2048
#define INDIM   1024
#define QH_     16
#define KVH_    4
#define HD_     64
#define G_      4
#define NKV     256
#define QSCALE  0.180336879f   // 0.125 * log2(e)

__device__ float g_Wqs[INDIM * NKV];
__device__ float g_Q[BB * KVH_ * SS * HD_];   // tf32-rounded, pre-scaled
__device__ float g_K[BB * KVH_ * SS * HD_];   // tf32-rounded
__device__ float g_V[BB * KVH_ * SS * HD_];   // tf32-rounded
__device__ float g_AO[BB * SS * NKV];

// --------------------------- helpers --------------------------------------
__device__ __forceinline__ unsigned f2tf(float f) {
    unsigned r;
    asm("cvt.rna.tf32.f32 %0, %1;" : "=r"(r) : "f"(f));
    return r;
}
__device__ __forceinline__ float ex2f(float x) {
    float y;
    asm("ex2.approx.f32 %0, %1;" : "=f"(y) : "f"(x));
    return y;
}
__device__ __forceinline__ void mma_tf32(float (&d)[4], const unsigned (&a)[4],
                                         const unsigned (&b)[2]) {
    asm volatile(
        "mma.sync.aligned.m16n8k8.row.col.f32.tf32.tf32.f32 "
        "{%0,%1,%2,%3}, {%4,%5,%6,%7}, {%8,%9}, {%0,%1,%2,%3};"
        : "+f"(d[0]), "+f"(d[1]), "+f"(d[2]), "+f"(d[3])
        : "r"(a[0]), "r"(a[1]), "r"(a[2]), "r"(a[3]), "r"(b[0]), "r"(b[1]));
}
__device__ __forceinline__ void cpa16(void* dst, const void* src) {
    unsigned d = (unsigned)__cvta_generic_to_shared(dst);
    asm volatile("cp.async.cg.shared.global [%0], [%1], 16;" :: "r"(d), "l"(src) : "memory");
}
#define CP_COMMIT() asm volatile("cp.async.commit_group;" ::: "memory")
#define CP_WAIT0()  asm volatile("cp.async.wait_group 0;" ::: "memory")
#define CP_WAIT1()  asm volatile("cp.async.wait_group 1;" ::: "memory")

// ---------------------------------------------------------------------------
// Fold Wq over group axis, with softmax scale folded in:
//   Wqs[i,h,d] = QSCALE * sum_g Wq[i, h*G+g, d]
// ---------------------------------------------------------------------------
__global__ void fold_wq_kernel(const float* __restrict__ Wq) {
    int idx = blockIdx.x * blockDim.x + threadIdx.x;
    if (idx >= INDIM * NKV) return;
    int i = idx >> 8;
    int n = idx & 255;
    int h = n >> 6, d = n & 63;
    const float* p = Wq + (size_t)i * (QH_ * HD_) + (size_t)(h * G_) * HD_ + d;
    g_Wqs[idx] = QSCALE * (p[0] + p[HD_] + p[2 * HD_] + p[3 * HD_]);
}

// ---------------------------------------------------------------------------
// tf32 GEMM via cp.async double buffer.
// C[4096,N] = A[4096,KD] * B[KD,N]; block 128x64, BK=16, 256 thr = 8 warps
// (4m x 2n), warp tile 32x32. A staged [m][k] pitch 20 (conflict-free frags),
// B staged [k][n] pitch 72. tf32 cvt at fragment load.
// SCATTER: write tf32-rounded to [b][h][s][d].
// ---------------------------------------------------------------------------
template<int KD, int N, bool SCATTER>
__device__ __forceinline__ void gemm_body(
        const float* __restrict__ A, const float* __restrict__ Bm,
        float* __restrict__ C) {
    __shared__ float As[2][128][20];
    __shared__ float Bs[2][16][72];

    int tid = threadIdx.x;
    int w = tid >> 5, lane = tid & 31, g = lane >> 2, qd = lane & 3;
    int wm = w & 3, wn = w >> 2;
    int m0 = blockIdx.y * 128, n0 = blockIdx.x * 64;

    // loader indices
    int ar = tid >> 1;                 // A row (two rows per... 2 chunks/thread)
    int ac = (tid & 1) * 8;            // A col within 16 (two 16B chunks)
    int br = tid >> 4;                 // B row 0..15
    int bc = (tid & 15) * 4;           // B col chunk

    const float* ApG = A + (size_t)(m0 + ar) * KD + ac;
    const float* BpG = Bm + (size_t)br * N + n0 + bc;

    float acc[2][4][4];
    #pragma unroll
    for (int mt = 0; mt < 2; mt++)
        #pragma unroll
        for (int nt = 0; nt < 4; nt++)
            #pragma unroll
            for (int e = 0; e < 4; e++) acc[mt][nt][e] = 0.f;

    // prologue: tile 0 -> buf 0
    cpa16(&As[0][ar][ac],     ApG);
    cpa16(&As[0][ar][ac + 4], ApG + 4);
    cpa16(&Bs[0][br][bc],     BpG);
    CP_COMMIT();

    const int KT = KD / 16;
    int buf = 0;
    #pragma unroll 1
    for (int t = 0; t < KT; t++) {
        if (t + 1 < KT) {
            int k0 = (t + 1) * 16;
            cpa16(&As[buf ^ 1][ar][ac],     ApG + k0);
            cpa16(&As[buf ^ 1][ar][ac + 4], ApG + k0 + 4);
            cpa16(&Bs[buf ^ 1][br][bc],     BpG + (size_t)k0 * N);
            CP_COMMIT();
            CP_WAIT1();
        } else {
            CP_WAIT0();
        }
        __syncthreads();

        #pragma unroll
        for (int ks = 0; ks < 2; ks++) {
            int kb = ks * 8;
            unsigned af[2][4];
            #pragma unroll
            for (int mt = 0; mt < 2; mt++) {
                int row = wm * 32 + mt * 16 + g;
                af[mt][0] = f2tf(As[buf][row][kb + qd]);
                af[mt][1] = f2tf(As[buf][row + 8][kb + qd]);
                af[mt][2] = f2tf(As[buf][row][kb + qd + 4]);
                af[mt][3] = f2tf(As[buf][row + 8][kb + qd + 4]);
            }
            unsigned bf[4][2];
            #pragma unroll
            for (int nt = 0; nt < 4; nt++) {
                int col = wn * 32 + nt * 8 + g;
                bf[nt][0] = f2tf(Bs[buf][kb + qd][col]);
                bf[nt][1] = f2tf(Bs[buf][kb + qd + 4][col]);
            }
            #pragma unroll
            for (int mt = 0; mt < 2; mt++)
                #pragma unroll
                for (int nt = 0; nt < 4; nt++)
                    mma_tf32(acc[mt][nt], af[mt], bf[nt]);
        }
        __syncthreads();
        buf ^= 1;
    }

    #pragma unroll
    for (int mt = 0; mt < 2; mt++) {
        #pragma unroll
        for (int nt = 0; nt < 4; nt++) {
            int row = m0 + wm * 32 + mt * 16 + g;
            int col = n0 + wn * 32 + nt * 8 + 2 * qd;
            if (SCATTER) {
                float2 lo = make_float2(__uint_as_float(f2tf(acc[mt][nt][0])),
                                        __uint_as_float(f2tf(acc[mt][nt][1])));
                float2 hi = make_float2(__uint_as_float(f2tf(acc[mt][nt][2])),
                                        __uint_as_float(f2tf(acc[mt][nt][3])));
                int b = row >> 11, s = row & 2047;
                int h = col >> 6, d = col & 63;
                size_t base = (((size_t)(b * KVH_ + h) * SS) << 6) + (size_t)d;
                *(float2*)&C[base + ((size_t)s << 6)]       = lo;
                *(float2*)&C[base + ((size_t)(s + 8) << 6)] = hi;
            } else {
                *(float2*)&C[(size_t)row * N + col] =
                    make_float2(acc[mt][nt][0], acc[mt][nt][1]);
                *(float2*)&C[(size_t)(row + 8) * N + col] =
                    make_float2(acc[mt][nt][2], acc[mt][nt][3]);
            }
        }
    }
}

__global__ void __launch_bounds__(256) qkv_gemm_kernel(
        const float* __restrict__ q_in, const float* __restrict__ kv_in,
        const float* __restrict__ Wk, const float* __restrict__ Wv,
        float* __restrict__ Q, float* __restrict__ K, float* __restrict__ V) {
    int z = blockIdx.z;
    const float* A  = (z == 0) ? q_in : kv_in;
    const float* Bm = (z == 0) ? g_Wqs : ((z == 1) ? Wk : Wv);
    float* C        = (z == 0) ? Q : ((z == 1) ? K : V);
    gemm_body<INDIM, NKV, true>(A, Bm, C);
}

__global__ void __launch_bounds__(256) out_gemm_kernel(
        const float* __restrict__ A, const float* __restrict__ Bm,
        float* __restrict__ C) {
    gemm_body<NKV, INDIM, false>(A, Bm, C);
}

// ---------------------------------------------------------------------------
// Causal flash attention, tf32 mma, cp.async double-buffered K/V.
// 128 thr = 4 warps; CTA = one 64-row q-tile; grid.x descending work order.
// Q/K/V already tf32-rounded (Q pre-scaled) -> raw 16B staging.
// Dynamic smem: K0,K1 (64x68), V0,V1 (64x72), P (64x68).
// ---------------------------------------------------------------------------
#define KP 68
#define VP 72
#define ATTN_SMEM ((2 * 64 * KP + 2 * 64 * VP + 64 * KP) * 4)

__global__ void __launch_bounds__(128) attn_kernel() {
    extern __shared__ unsigned smp[];
    unsigned* Kb0 = smp;
    unsigned* Kb1 = Kb0 + 64 * KP;
    unsigned* Vb0 = Kb1 + 64 * KP;
    unsigned* Vb1 = Vb0 + 64 * VP;
    unsigned* Pb  = Vb1 + 64 * VP;

    int bh = blockIdx.y;
    int qt = (SS / 64 - 1) - blockIdx.x;   // longest first
    int q0 = qt * 64;
    const float* Qh = g_Q + (size_t)bh * SS * HD_;
    const float* Kh = g_K + (size_t)bh * SS * HD_;
    const float* Vh = g_V + (size_t)bh * SS * HD_;

    int tid = threadIdx.x;
    int w = tid >> 5, lane = tid & 31, g = lane >> 2, qd = lane & 3;
    int r0 = w * 16 + g;
    int b = bh >> 2, h = bh & 3;
    int lr = tid >> 4, lc = tid & 15;

    // stage Q (raw copy: already tf32+scaled)
    {
        const uint4* Qsrc = (const uint4*)(Qh + (size_t)q0 * 64);
        #pragma unroll
        for (int it = 0; it < 8; it++) {
            int r = lr + it * 8;
            *(uint4*)&Pb[r * KP + lc * 4] = Qsrc[r * 16 + lc];
        }
    }
    __syncthreads();

    unsigned qf[8][4];
    #pragma unroll
    for (int ks = 0; ks < 8; ks++) {
        qf[ks][0] = Pb[r0 * KP + ks * 8 + qd];
        qf[ks][1] = Pb[(r0 + 8) * KP + ks * 8 + qd];
        qf[ks][2] = Pb[r0 * KP + ks * 8 + qd + 4];
        qf[ks][3] = Pb[(r0 + 8) * KP + ks * 8 + qd + 4];
    }

    float m0 = -3.0e38f, m1 = -3.0e38f, l0 = 0.f, l1 = 0.f;
    float oacc[8][4];
    #pragma unroll
    for (int dt = 0; dt < 8; dt++)
        #pragma unroll
        for (int e = 0; e < 4; e++) oacc[dt][e] = 0.f;

    // prologue: tile 0
    {
        const float* Ksrc = Kh; const float* Vsrc = Vh;
        #pragma unroll
        for (int it = 0; it < 8; it++) {
            int r = lr + it * 8;
            cpa16(&Kb0[r * KP + lc * 4], Ksrc + r * 64 + lc * 4);
            cpa16(&Vb0[r * VP + lc * 4], Vsrc + r * 64 + lc * 4);
        }
    }
    CP_COMMIT();

    #pragma unroll 1
    for (int kt = 0; kt <= qt; kt++) {
        unsigned* Kc = (kt & 1) ? Kb1 : Kb0;
        unsigned* Vc = (kt & 1) ? Vb1 : Vb0;
        if (kt < qt) {
            unsigned* Kn = (kt & 1) ? Kb0 : Kb1;
            unsigned* Vn = (kt & 1) ? Vb0 : Vb1;
            const float* Ksrc = Kh + (size_t)(kt + 1) * 4096;
            const float* Vsrc = Vh + (size_t)(kt + 1) * 4096;
            #pragma unroll
            for (int it = 0; it < 8; it++) {
                int r = lr + it * 8;
                cpa16(&Kn[r * KP + lc * 4], Ksrc + r * 64 + lc * 4);
                cpa16(&Vn[r * VP + lc * 4], Vsrc + r * 64 + lc * 4);
            }
            CP_COMMIT();
            CP_WAIT1();
        } else {
            CP_WAIT0();
        }
        __syncthreads();

        // --- S = Q K^T ---
        float sacc[8][4];
        #pragma unroll
        for (int nt = 0; nt < 8; nt++)
            #pragma unroll
            for (int e = 0; e < 4; e++) sacc[nt][e] = 0.f;
        #pragma unroll
        for (int nt = 0; nt < 8; nt++) {
            #pragma unroll
            for (int ks = 0; ks < 8; ks++) {
                unsigned kb[2];
                kb[0] = Kc[(nt * 8 + g) * KP + ks * 8 + qd];
                kb[1] = Kc[(nt * 8 + g) * KP + ks * 8 + qd + 4];
                mma_tf32(sacc[nt], qf[ks], kb);
            }
        }

        if (kt == qt) {
            int grow0 = q0 + r0;
            #pragma unroll
            for (int nt = 0; nt < 8; nt++) {
                int col = kt * 64 + nt * 8 + 2 * qd;
                if (col     > grow0)     sacc[nt][0] = -1.0e30f;
                if (col + 1 > grow0)     sacc[nt][1] = -1.0e30f;
                if (col     > grow0 + 8) sacc[nt][2] = -1.0e30f;
                if (col + 1 > grow0 + 8) sacc[nt][3] = -1.0e30f;
            }
        }

        // --- online softmax (exp2 domain) ---
        float mx0 = -3.0e38f, mx1 = -3.0e38f;
        #pragma unroll
        for (int nt = 0; nt < 8; nt++) {
            mx0 = fmaxf(mx0, fmaxf(sacc[nt][0], sacc[nt][1]));
            mx1 = fmaxf(mx1, fmaxf(sacc[nt][2], sacc[nt][3]));
        }
        mx0 = fmaxf(mx0, __shfl_xor_sync(0xffffffffu, mx0, 1));
        mx0 = fmaxf(mx0, __shfl_xor_sync(0xffffffffu, mx0, 2));
        mx1 = fmaxf(mx1, __shfl_xor_sync(0xffffffffu, mx1, 1));
        mx1 = fmaxf(mx1, __shfl_xor_sync(0xffffffffu, mx1, 2));
        float mn0 = fmaxf(m0, mx0), mn1 = fmaxf(m1, mx1);
        float c0 = ex2f(m0 - mn0), c1 = ex2f(m1 - mn1);
        m0 = mn0; m1 = mn1;
        float rs0 = 0.f, rs1 = 0.f;
        #pragma unroll
        for (int nt = 0; nt < 8; nt++) {
            float p0 = ex2f(sacc[nt][0] - mn0);
            float p1 = ex2f(sacc[nt][1] - mn0);
            float p2 = ex2f(sacc[nt][2] - mn1);
            float p3 = ex2f(sacc[nt][3] - mn1);
            sacc[nt][0] = p0; sacc[nt][1] = p1;
            sacc[nt][2] = p2; sacc[nt][3] = p3;
            rs0 += p0 + p1; rs1 += p2 + p3;
        }
        rs0 += __shfl_xor_sync(0xffffffffu, rs0, 1);
        rs0 += __shfl_xor_sync(0xffffffffu, rs0, 2);
        rs1 += __shfl_xor_sync(0xffffffffu, rs1, 1);
        rs1 += __shfl_xor_sync(0xffffffffu, rs1, 2);
        l0 = l0 * c0 + rs0;
        l1 = l1 * c1 + rs1;
        #pragma unroll
        for (int dt = 0; dt < 8; dt++) {
            oacc[dt][0] *= c0; oacc[dt][1] *= c0;
            oacc[dt][2] *= c1; oacc[dt][3] *= c1;
        }

        // --- P to own buffer (warp-local rows) ---
        #pragma unroll
        for (int nt = 0; nt < 8; nt++) {
            uint2 u0, u1;
            u0.x = f2tf(sacc[nt][0]); u0.y = f2tf(sacc[nt][1]);
            u1.x = f2tf(sacc[nt][2]); u1.y = f2tf(sacc[nt][3]);
            *(uint2*)&Pb[r0 * KP + nt * 8 + 2 * qd]       = u0;
            *(uint2*)&Pb[(r0 + 8) * KP + nt * 8 + 2 * qd] = u1;
        }
        __syncwarp();

        unsigned pa[8][4];
        #pragma unroll
        for (int ks = 0; ks < 8; ks++) {
            pa[ks][0] = Pb[r0 * KP + ks * 8 + qd];
            pa[ks][1] = Pb[(r0 + 8) * KP + ks * 8 + qd];
            pa[ks][2] = Pb[r0 * KP + ks * 8 + qd + 4];
            pa[ks][3] = Pb[(r0 + 8) * KP + ks * 8 + qd + 4];
        }
        #pragma unroll
        for (int dt = 0; dt < 8; dt++) {
            #pragma unroll
            for (int ks = 0; ks < 8; ks++) {
                unsigned vb[2];
                vb[0] = Vc[(ks * 8 + qd) * VP + dt * 8 + g];
                vb[1] = Vc[(ks * 8 + qd + 4) * VP + dt * 8 + g];
                mma_tf32(oacc[dt], pa[ks], vb);
            }
        }
        __syncthreads();   // all reads of Kc/Vc done before next prefetch reuse
    }

    // --- epilogue ---
    float il0 = 1.0f / l0, il1 = 1.0f / l1;
    int grow = q0 + r0;
    size_t base0 = (((size_t)b * SS + grow) << 8) + (size_t)(h << 6);
    size_t base1 = (((size_t)b * SS + grow + 8) << 8) + (size_t)(h << 6);
    #pragma unroll
    for (int dt = 0; dt < 8; dt++) {
        int d = dt * 8 + 2 * qd;
        *(float2*)&g_AO[base0 + d] =
            make_float2(oacc[dt][0] * il0, oacc[dt][1] * il0);
        *(float2*)&g_AO[base1 + d] =
            make_float2(oacc[dt][2] * il1, oacc[dt][3] * il1);
    }
}

extern "C" void kernel_launch(void* const* d_in, const int* in_sizes, int n_in,
                              void* d_out, int out_size) {
    const float* q_in  = (const float*)d_in[0];
    const float* kv_in = (const float*)d_in[1];
    const float* Wq    = (const float*)d_in[3];
    const float* Wk    = (const float*)d_in[4];
    const float* Wv    = (const float*)d_in[5];
    const float* Wo    = (const float*)d_in[6];
    float* out = (float*)d_out;

    float *pQ, *pK, *pV, *pAO;
    cudaGetSymbolAddress((void**)&pQ,  g_Q);
    cudaGetSymbolAddress((void**)&pK,  g_K);
    cudaGetSymbolAddress((void**)&pV,  g_V);
    cudaGetSymbolAddress((void**)&pAO, g_AO);

    cudaFuncSetAttribute(attn_kernel,
                         cudaFuncAttributeMaxDynamicSharedMemorySize, ATTN_SMEM);

    fold_wq_kernel<<<(INDIM * NKV + 255) / 256, 256>>>(Wq);

    dim3 gqkv(NKV / 64, (BB * SS) / 128, 3);   // (4, 32, 3)
    qkv_gemm_kernel<<<gqkv, 256>>>(q_in, kv_in, Wk, Wv, pQ, pK, pV);

    attn_kernel<<<dim3(SS / 64, BB * KVH_), 128, ATTN_SMEM>>>();

    out_gemm_kernel<<<dim3(INDIM / 64, (BB * SS) / 128), 256>>>(pAO, Wo, out);
}